// round 2
// baseline (speedup 1.0000x reference)
#include <cuda_runtime.h>
#include <cstdint>
#include <math.h>

// Problem constants (fixed shapes)
#define SDIM   2048
#define LDIM   3
#define DDIM   128
#define NKDIM  16
#define VOC    50000
#define NTOK   (SDIM*LDIM)      // 6144
#define NPART  48               // 6144 / 128

// ---------------- device scratch (static, allocation-free) ----------------
__device__ float g_partial[NPART*DDIM];
__device__ float g_Eu[DDIM];
__device__ float g_usrT[DDIM*SDIM];      // u_attn transposed [k][s]
__device__ float g_c[VOC];               // c[v] = fc2b[v] + Eu . fc2W[v,:128]
__device__ float g_w2T[DDIM*VOC];        // fc2W[:,128:256] transposed [k][v]

// ---------------- packed f32x2 helpers ----------------
__device__ __forceinline__ unsigned long long pack2(float a){
    unsigned long long r; unsigned u = __float_as_uint(a);
    asm("mov.b64 %0, {%1, %1};" : "=l"(r) : "r"(u));
    return r;
}
__device__ __forceinline__ unsigned long long fma2(unsigned long long a,
                                                   unsigned long long b,
                                                   unsigned long long c){
    unsigned long long d;
    asm("fma.rn.f32x2 %0, %1, %2, %3;" : "=l"(d) : "l"(a), "l"(b), "l"(c));
    return d;
}

// ---------------- Eu = mean of emb[su] over all 6144 tokens ----------------
__global__ void k_eu_partial(const int* __restrict__ su, const float* __restrict__ emb){
    __shared__ int sIdx[128];
    int tid = threadIdx.x;
    sIdx[tid] = su[blockIdx.x*128 + tid];
    __syncthreads();
    float sum = 0.f;
    #pragma unroll 4
    for (int t = 0; t < 128; t++)
        sum += emb[(size_t)sIdx[t]*DDIM + tid];
    g_partial[blockIdx.x*DDIM + tid] = sum;
}

__global__ void k_eu_final(){
    int tid = threadIdx.x;
    float s = 0.f;
    #pragma unroll
    for (int b = 0; b < NPART; b++) s += g_partial[b*DDIM + tid];
    g_Eu[tid] = s * (1.0f / (float)NTOK);
}

// ---------------- per-position middle network: one CTA per s ----------------
// NOTE: the reference's attention block collapses: attn[i,d] == Ec[i,d]
// (softmax rows sum to 1 under the reference's broadcasting), so fc1 input
// is simply [conv(16) | Ec flattened(384)].
__global__ void __launch_bounds__(128) k_mid(
    const int*  __restrict__ su,   const float* __restrict__ emb,
    const float* __restrict__ convK, const float* __restrict__ convb,
    const float* __restrict__ fc1W, const float* __restrict__ fc1b)
{
    const int s   = blockIdx.x;
    const int tid = threadIdx.x;
    const int w   = tid >> 5, lane = tid & 31;

    __shared__ float sIn[NKDIM + LDIM*DDIM];  // fc1 input: [conv(16) | Ec(384)]
    __shared__ float sH[DDIM];
    __shared__ float sMM[4][2];

    float* sEc = sIn + NKDIM;                 // Ec lives directly in fc1 input

    // gather Ec
    #pragma unroll
    for (int l = 0; l < LDIM; l++)
        sEc[l*DDIM + tid] = emb[(size_t)su[s*LDIM + l]*DDIM + tid];
    __syncthreads();

    // VerticalConv: warp w handles kernels k = 4w..4w+3
    #pragma unroll
    for (int kk = 0; kk < 4; kk++){
        int k = w*4 + kk;
        float acc = 0.f;
        #pragma unroll
        for (int j = lane; j < LDIM*DDIM; j += 32)
            acc += sEc[j] * convK[k*(LDIM*DDIM) + j];
        #pragma unroll
        for (int o = 16; o; o >>= 1) acc += __shfl_xor_sync(0xffffffffu, acc, o);
        if (lane == 0) sIn[k] = fmaxf(acc + convb[k], 0.f);
    }
    __syncthreads();

    // fc1: h[e] = relu(fc1b[e] + fc1W[e,:] . sIn)
    float h;
    {
        float acc = fc1b[tid];
        const float4* w4 = (const float4*)(fc1W + (size_t)tid*(NKDIM+LDIM*DDIM));
        #pragma unroll 10
        for (int j4 = 0; j4 < (NKDIM+LDIM*DDIM)/4; j4++){
            float4 a = w4[j4];
            const float* in = sIn + j4*4;
            acc = fmaf(a.x,in[0],fmaf(a.y,in[1],fmaf(a.z,in[2],fmaf(a.w,in[3],acc))));
        }
        h = fmaxf(acc, 0.f);
        sH[tid] = h;
        float mx = h, mn = h;
        #pragma unroll
        for (int o = 16; o; o >>= 1){
            mx = fmaxf(mx, __shfl_xor_sync(0xffffffffu, mx, o));
            mn = fminf(mn, __shfl_xor_sync(0xffffffffu, mn, o));
        }
        if (lane == 0){ sMM[w][0] = mx; sMM[w][1] = mn; }
    }
    __syncthreads();
    float hmax = fmaxf(fmaxf(sMM[0][0],sMM[1][0]), fmaxf(sMM[2][0],sMM[3][0]));
    float hmin = fminf(fminf(sMM[0][1],sMM[1][1]), fminf(sMM[2][1],sMM[3][1]));

    // u_attn[p] = softmax_q(Eu[p]*h[q]) . h    (h >= 0 so max is at hmax/hmin)
    float a = g_Eu[tid];
    float m = (a > 0.f) ? a*hmax : a*hmin;
    float den = 0.f, num = 0.f;
    #pragma unroll 8
    for (int q = 0; q < DDIM; q++){
        float hq = sH[q];
        float t = __expf(fmaf(a, hq, -m));
        den += t;
        num = fmaf(t, hq, num);
    }
    g_usrT[tid*SDIM + s] = num/den;   // transposed store for GEMM A-tile
}

// ---------------- transpose fc2W[:,128:256] -> w2T[k][v] ----------------
__global__ void k_transpose(const float* __restrict__ fc2W){
    __shared__ float tile[32][33];
    int tx = threadIdx.x, ty = threadIdx.y;  // (32, 8)
    int bv = blockIdx.x, bk = blockIdx.y;
    #pragma unroll
    for (int r = 0; r < 4; r++){
        int v = bv*32 + ty + r*8;
        int k = bk*32 + tx;
        tile[ty+r*8][tx] = (v < VOC) ? fc2W[(size_t)v*256 + 128 + k] : 0.f;
    }
    __syncthreads();
    #pragma unroll
    for (int r = 0; r < 4; r++){
        int k = bk*32 + ty + r*8;
        int v = bv*32 + tx;
        if (v < VOC) g_w2T[(size_t)k*VOC + v] = tile[tx][ty+r*8];
    }
}

// ---------------- c[v] = fc2b[v] + Eu . fc2W[v,:128] ----------------
__global__ void k_cvec(const float* __restrict__ fc2W, const float* __restrict__ fc2b){
    __shared__ float sEu[DDIM];
    int tid = threadIdx.x;
    if (tid < DDIM) sEu[tid] = g_Eu[tid];
    __syncthreads();
    int w = tid >> 5, lane = tid & 31;
    int v = blockIdx.x*8 + w;
    float4 ww = *(const float4*)(fc2W + (size_t)v*256 + lane*4);
    float4 ee = *(const float4*)(sEu + lane*4);
    float acc = ww.x*ee.x + ww.y*ee.y + ww.z*ee.z + ww.w*ee.w;
    #pragma unroll
    for (int o = 16; o; o >>= 1) acc += __shfl_xor_sync(0xffffffffu, acc, o);
    if (lane == 0) g_c[v] = acc + fc2b[v];
}

// ---------------- main GEMM: out[s][v] = c[v] + usrT[:,s] . w2T[:,v] ----------------
// CTA tile 128(M) x 256(N), K=128 fully staged. 256 threads, 8x16 per thread,
// packed f32x2 FMA (2 FMAs/instr).
__global__ void __launch_bounds__(256, 1) k_gemm(float* __restrict__ out){
    extern __shared__ float smem[];
    float* As = smem;                 // [128][128]  (k-major)
    float* Bs = smem + 128*128;       // [128][256]  (k-major)

    const int tid = threadIdx.x;
    const int bm = blockIdx.y * 128;
    const int bn = blockIdx.x * 256;

    // load A tile (coalesced, conflict-free)
    #pragma unroll
    for (int p = 0; p < 16; p++){
        int lin = p*256 + tid;            // 0..4095 float4s, lin = k*32 + c4
        int k = lin >> 5, c4 = lin & 31;
        ((float4*)As)[lin] = *(const float4*)(g_usrT + (size_t)k*SDIM + bm + c4*4);
    }
    // load B tile (coalesced, conflict-free)
    #pragma unroll
    for (int p = 0; p < 32; p++){
        int lin = p*256 + tid;            // 0..8191 float4s, lin = k*64 + c4
        int k = lin >> 6, c4 = lin & 63;
        int v = bn + c4*4;
        float4 val = (v < VOC) ? *(const float4*)(g_w2T + (size_t)k*VOC + v)
                               : make_float4(0.f,0.f,0.f,0.f);
        ((float4*)Bs)[lin] = val;
    }
    __syncthreads();

    const int tn = tid & 15, tm = tid >> 4;
    unsigned long long acc[8][8];
    #pragma unroll
    for (int i = 0; i < 8; i++)
        #pragma unroll
        for (int j = 0; j < 8; j++) acc[i][j] = 0ull;

    const float* Ab = As + tm*8;
    const float* Bb = Bs + tn*16;
    #pragma unroll 4
    for (int k = 0; k < 128; k++){
        float4 a0 = *(const float4*)(Ab + k*128);
        float4 a1 = *(const float4*)(Ab + k*128 + 4);
        ulonglong2 b0 = *(const ulonglong2*)(Bb + k*256);
        ulonglong2 b1 = *(const ulonglong2*)(Bb + k*256 + 4);
        ulonglong2 b2 = *(const ulonglong2*)(Bb + k*256 + 8);
        ulonglong2 b3 = *(const ulonglong2*)(Bb + k*256 + 12);
        unsigned long long bb[8] = {b0.x,b0.y,b1.x,b1.y,b2.x,b2.y,b3.x,b3.y};
        float av[8] = {a0.x,a0.y,a0.z,a0.w,a1.x,a1.y,a1.z,a1.w};
        #pragma unroll
        for (int i = 0; i < 8; i++){
            unsigned long long ap = pack2(av[i]);
            #pragma unroll
            for (int j = 0; j < 8; j++)
                acc[i][j] = fma2(ap, bb[j], acc[i][j]);
        }
    }

    // epilogue: add c[v], write float2
    #pragma unroll
    for (int i = 0; i < 8; i++){
        int m = bm + tm*8 + i;
        float* orow = out + (size_t)m * VOC;
        #pragma unroll
        for (int j = 0; j < 8; j++){
            int v = bn + tn*16 + j*2;
            if (v < VOC){
                float2 cc = *(const float2*)(g_c + v);
                float2 r;
                r.x = __uint_as_float((unsigned)(acc[i][j] & 0xffffffffull)) + cc.x;
                r.y = __uint_as_float((unsigned)(acc[i][j] >> 32))           + cc.y;
                *(float2*)(orow + v) = r;
            }
        }
    }
}

// ---------------- launch ----------------
extern "C" void kernel_launch(void* const* d_in, const int* in_sizes, int n_in,
                              void* d_out, int out_size){
    const int*   su    = (const int*)  d_in[0];
    const float* emb   = (const float*)d_in[1];
    const float* convK = (const float*)d_in[2];
    const float* convb = (const float*)d_in[3];
    const float* fc1W  = (const float*)d_in[7];
    const float* fc1b  = (const float*)d_in[8];
    const float* fc2W  = (const float*)d_in[9];
    const float* fc2b  = (const float*)d_in[10];
    float* out = (float*)d_out;

    (void)in_sizes; (void)n_in; (void)out_size;

    cudaFuncSetAttribute(k_gemm, cudaFuncAttributeMaxDynamicSharedMemorySize, 196608);

    k_eu_partial<<<NPART, 128>>>(su, emb);
    k_eu_final<<<1, 128>>>();
    k_mid<<<SDIM, 128>>>(su, emb, convK, convb, fc1W, fc1b);
    k_transpose<<<dim3((VOC+31)/32, DDIM/32), dim3(32, 8)>>>(fc2W);
    k_cvec<<<VOC/8, 256>>>(fc2W, fc2b);
    k_gemm<<<dim3((VOC+255)/256, SDIM/128), 256, 196608>>>(out);
}

// round 3
// speedup vs baseline: 1.0022x; 1.0022x over previous
#include <cuda_runtime.h>
#include <cstdint>
#include <math.h>

// Problem constants (fixed shapes)
#define SDIM   2048
#define LDIM   3
#define DDIM   128
#define NKDIM  16
#define VOC    50000
#define NTOK   (SDIM*LDIM)      // 6144
#define NPART  48               // 6144 / 128

// ---------------- device scratch (static, allocation-free) ----------------
__device__ float g_partial[NPART*DDIM];
__device__ float g_Eu[DDIM];
__device__ float g_usrT[DDIM*SDIM];      // u_attn transposed [k][s]
__device__ float g_c[VOC];               // c[v] = fc2b[v] + Eu . fc2W[v,:128]
__device__ float g_w2T[DDIM*VOC];        // fc2W[:,128:256] transposed [k][v]

// ---------------- packed f32x2 helpers ----------------
__device__ __forceinline__ unsigned long long pack2(float a){
    unsigned long long r; unsigned u = __float_as_uint(a);
    asm("mov.b64 %0, {%1, %1};" : "=l"(r) : "r"(u));
    return r;
}
__device__ __forceinline__ unsigned long long fma2(unsigned long long a,
                                                   unsigned long long b,
                                                   unsigned long long c){
    unsigned long long d;
    asm("fma.rn.f32x2 %0, %1, %2, %3;" : "=l"(d) : "l"(a), "l"(b), "l"(c));
    return d;
}

// ---------------- Eu = mean of emb[su] over all 6144 tokens ----------------
__global__ void k_eu_partial(const int* __restrict__ su, const float* __restrict__ emb){
    __shared__ int sIdx[128];
    int tid = threadIdx.x;
    sIdx[tid] = su[blockIdx.x*128 + tid];
    __syncthreads();
    float sum = 0.f;
    #pragma unroll 4
    for (int t = 0; t < 128; t++)
        sum += emb[(size_t)sIdx[t]*DDIM + tid];
    g_partial[blockIdx.x*DDIM + tid] = sum;
}

__global__ void k_eu_final(){
    int tid = threadIdx.x;
    float s = 0.f;
    #pragma unroll
    for (int b = 0; b < NPART; b++) s += g_partial[b*DDIM + tid];
    g_Eu[tid] = s * (1.0f / (float)NTOK);
}

// ---------------- per-position middle network: one CTA per s ----------------
// NOTE: the reference's attention block collapses: attn[i,d] == Ec[i,d]
// (softmax rows sum to 1 under the reference's broadcasting), so fc1 input
// is simply [conv(16) | Ec flattened(384)].
__global__ void __launch_bounds__(128) k_mid(
    const int*  __restrict__ su,   const float* __restrict__ emb,
    const float* __restrict__ convK, const float* __restrict__ convb,
    const float* __restrict__ fc1W, const float* __restrict__ fc1b)
{
    const int s   = blockIdx.x;
    const int tid = threadIdx.x;
    const int w   = tid >> 5, lane = tid & 31;

    __shared__ float sIn[NKDIM + LDIM*DDIM];  // fc1 input: [conv(16) | Ec(384)]
    __shared__ float sH[DDIM];
    __shared__ float sMM[4][2];

    float* sEc = sIn + NKDIM;                 // Ec lives directly in fc1 input

    // gather Ec
    #pragma unroll
    for (int l = 0; l < LDIM; l++)
        sEc[l*DDIM + tid] = emb[(size_t)su[s*LDIM + l]*DDIM + tid];
    __syncthreads();

    // VerticalConv: warp w handles kernels k = 4w..4w+3
    #pragma unroll
    for (int kk = 0; kk < 4; kk++){
        int k = w*4 + kk;
        float acc = 0.f;
        #pragma unroll
        for (int j = lane; j < LDIM*DDIM; j += 32)
            acc += sEc[j] * convK[k*(LDIM*DDIM) + j];
        #pragma unroll
        for (int o = 16; o; o >>= 1) acc += __shfl_xor_sync(0xffffffffu, acc, o);
        if (lane == 0) sIn[k] = fmaxf(acc + convb[k], 0.f);
    }
    __syncthreads();

    // fc1: h[e] = relu(fc1b[e] + fc1W[e,:] . sIn)
    float h;
    {
        float acc = fc1b[tid];
        const float4* w4 = (const float4*)(fc1W + (size_t)tid*(NKDIM+LDIM*DDIM));
        #pragma unroll 10
        for (int j4 = 0; j4 < (NKDIM+LDIM*DDIM)/4; j4++){
            float4 a = w4[j4];
            const float* in = sIn + j4*4;
            acc = fmaf(a.x,in[0],fmaf(a.y,in[1],fmaf(a.z,in[2],fmaf(a.w,in[3],acc))));
        }
        h = fmaxf(acc, 0.f);
        sH[tid] = h;
        float mx = h, mn = h;
        #pragma unroll
        for (int o = 16; o; o >>= 1){
            mx = fmaxf(mx, __shfl_xor_sync(0xffffffffu, mx, o));
            mn = fminf(mn, __shfl_xor_sync(0xffffffffu, mn, o));
        }
        if (lane == 0){ sMM[w][0] = mx; sMM[w][1] = mn; }
    }
    __syncthreads();
    float hmax = fmaxf(fmaxf(sMM[0][0],sMM[1][0]), fmaxf(sMM[2][0],sMM[3][0]));
    float hmin = fminf(fminf(sMM[0][1],sMM[1][1]), fminf(sMM[2][1],sMM[3][1]));

    // u_attn[p] = softmax_q(Eu[p]*h[q]) . h    (h >= 0 so max is at hmax/hmin)
    float a = g_Eu[tid];
    float m = (a > 0.f) ? a*hmax : a*hmin;
    float den = 0.f, num = 0.f;
    #pragma unroll 8
    for (int q = 0; q < DDIM; q++){
        float hq = sH[q];
        float t = __expf(fmaf(a, hq, -m));
        den += t;
        num = fmaf(t, hq, num);
    }
    g_usrT[tid*SDIM + s] = num/den;   // transposed store for GEMM A-tile
}

// ---------------- transpose fc2W[:,128:256] -> w2T[k][v] ----------------
__global__ void k_transpose(const float* __restrict__ fc2W){
    __shared__ float tile[32][33];
    int tx = threadIdx.x, ty = threadIdx.y;  // (32, 8)
    int bv = blockIdx.x, bk = blockIdx.y;
    #pragma unroll
    for (int r = 0; r < 4; r++){
        int v = bv*32 + ty + r*8;
        int k = bk*32 + tx;
        tile[ty+r*8][tx] = (v < VOC) ? fc2W[(size_t)v*256 + 128 + k] : 0.f;
    }
    __syncthreads();
    #pragma unroll
    for (int r = 0; r < 4; r++){
        int k = bk*32 + ty + r*8;
        int v = bv*32 + tx;
        if (v < VOC) g_w2T[(size_t)k*VOC + v] = tile[tx][ty+r*8];
    }
}

// ---------------- c[v] = fc2b[v] + Eu . fc2W[v,:128] ----------------
__global__ void k_cvec(const float* __restrict__ fc2W, const float* __restrict__ fc2b){
    __shared__ float sEu[DDIM];
    int tid = threadIdx.x;
    if (tid < DDIM) sEu[tid] = g_Eu[tid];
    __syncthreads();
    int w = tid >> 5, lane = tid & 31;
    int v = blockIdx.x*8 + w;
    float4 ww = *(const float4*)(fc2W + (size_t)v*256 + lane*4);
    float4 ee = *(const float4*)(sEu + lane*4);
    float acc = ww.x*ee.x + ww.y*ee.y + ww.z*ee.z + ww.w*ee.w;
    #pragma unroll
    for (int o = 16; o; o >>= 1) acc += __shfl_xor_sync(0xffffffffu, acc, o);
    if (lane == 0) g_c[v] = acc + fc2b[v];
}

// ---------------- main GEMM: out[s][v] = c[v] + usrT[:,s] . w2T[:,v] ----------------
// CTA tile 128(M) x 256(N), K=128 fully staged. 256 threads, 8x16 per thread,
// packed f32x2 FMA (2 FMAs/instr).
__global__ void __launch_bounds__(256, 1) k_gemm(float* __restrict__ out){
    extern __shared__ float smem[];
    float* As = smem;                 // [128][128]  (k-major)
    float* Bs = smem + 128*128;       // [128][256]  (k-major)

    const int tid = threadIdx.x;
    const int bm = blockIdx.y * 128;
    const int bn = blockIdx.x * 256;

    // load A tile (coalesced, conflict-free)
    #pragma unroll
    for (int p = 0; p < 16; p++){
        int lin = p*256 + tid;            // 0..4095 float4s, lin = k*32 + c4
        int k = lin >> 5, c4 = lin & 31;
        ((float4*)As)[lin] = *(const float4*)(g_usrT + (size_t)k*SDIM + bm + c4*4);
    }
    // load B tile (coalesced, conflict-free)
    #pragma unroll
    for (int p = 0; p < 32; p++){
        int lin = p*256 + tid;            // 0..8191 float4s, lin = k*64 + c4
        int k = lin >> 6, c4 = lin & 63;
        int v = bn + c4*4;
        float4 val = (v < VOC) ? *(const float4*)(g_w2T + (size_t)k*VOC + v)
                               : make_float4(0.f,0.f,0.f,0.f);
        ((float4*)Bs)[lin] = val;
    }
    __syncthreads();

    const int tn = tid & 15, tm = tid >> 4;
    unsigned long long acc[8][8];
    #pragma unroll
    for (int i = 0; i < 8; i++)
        #pragma unroll
        for (int j = 0; j < 8; j++) acc[i][j] = 0ull;

    const float* Ab = As + tm*8;
    const float* Bb = Bs + tn*16;
    #pragma unroll 4
    for (int k = 0; k < 128; k++){
        float4 a0 = *(const float4*)(Ab + k*128);
        float4 a1 = *(const float4*)(Ab + k*128 + 4);
        ulonglong2 b0 = *(const ulonglong2*)(Bb + k*256);
        ulonglong2 b1 = *(const ulonglong2*)(Bb + k*256 + 4);
        ulonglong2 b2 = *(const ulonglong2*)(Bb + k*256 + 8);
        ulonglong2 b3 = *(const ulonglong2*)(Bb + k*256 + 12);
        unsigned long long bb[8] = {b0.x,b0.y,b1.x,b1.y,b2.x,b2.y,b3.x,b3.y};
        float av[8] = {a0.x,a0.y,a0.z,a0.w,a1.x,a1.y,a1.z,a1.w};
        #pragma unroll
        for (int i = 0; i < 8; i++){
            unsigned long long ap = pack2(av[i]);
            #pragma unroll
            for (int j = 0; j < 8; j++)
                acc[i][j] = fma2(ap, bb[j], acc[i][j]);
        }
    }

    // epilogue: add c[v], write float2
    #pragma unroll
    for (int i = 0; i < 8; i++){
        int m = bm + tm*8 + i;
        float* orow = out + (size_t)m * VOC;
        #pragma unroll
        for (int j = 0; j < 8; j++){
            int v = bn + tn*16 + j*2;
            if (v < VOC){
                float2 cc = *(const float2*)(g_c + v);
                float2 r;
                r.x = __uint_as_float((unsigned)(acc[i][j] & 0xffffffffull)) + cc.x;
                r.y = __uint_as_float((unsigned)(acc[i][j] >> 32))           + cc.y;
                *(float2*)(orow + v) = r;
            }
        }
    }
}

// ---------------- launch ----------------
extern "C" void kernel_launch(void* const* d_in, const int* in_sizes, int n_in,
                              void* d_out, int out_size){
    const int*   su    = (const int*)  d_in[0];
    const float* emb   = (const float*)d_in[1];
    const float* convK = (const float*)d_in[2];
    const float* convb = (const float*)d_in[3];
    const float* fc1W  = (const float*)d_in[7];
    const float* fc1b  = (const float*)d_in[8];
    const float* fc2W  = (const float*)d_in[9];
    const float* fc2b  = (const float*)d_in[10];
    float* out = (float*)d_out;

    (void)in_sizes; (void)n_in; (void)out_size;

    cudaFuncSetAttribute(k_gemm, cudaFuncAttributeMaxDynamicSharedMemorySize, 196608);

    k_eu_partial<<<NPART, 128>>>(su, emb);
    k_eu_final<<<1, 128>>>();
    k_mid<<<SDIM, 128>>>(su, emb, convK, convb, fc1W, fc1b);
    k_transpose<<<dim3((VOC+31)/32, DDIM/32), dim3(32, 8)>>>(fc2W);
    k_cvec<<<VOC/8, 256>>>(fc2W, fc2b);
    k_gemm<<<dim3((VOC+255)/256, SDIM/128), 256, 196608>>>(out);
}

// round 4
// speedup vs baseline: 1.7143x; 1.7105x over previous
#include <cuda_runtime.h>
#include <cstdint>
#include <math.h>

// Problem constants (fixed shapes)
#define SDIM   2048
#define LDIM   3
#define DDIM   128
#define NKDIM  16
#define VOC    50000
#define NTOK   (SDIM*LDIM)      // 6144
#define NPART  48               // 6144 / 128

// ---------------- device scratch (static, allocation-free) ----------------
__device__ float g_partial[NPART*DDIM];
__device__ float g_Eu[DDIM];
__device__ float g_usrT[DDIM*SDIM];      // u_attn transposed [k][s]
__device__ float g_c[VOC];               // c[v] = fc2b[v] + Eu . fc2W[v,:128]
__device__ float g_w2T[DDIM*VOC];        // fc2W[:,128:256] transposed [k][v]

// ---------------- packed f32x2 helpers ----------------
__device__ __forceinline__ unsigned long long pack2(float a){
    unsigned long long r; unsigned u = __float_as_uint(a);
    asm("mov.b64 %0, {%1, %1};" : "=l"(r) : "r"(u));
    return r;
}
__device__ __forceinline__ unsigned long long fma2(unsigned long long a,
                                                   unsigned long long b,
                                                   unsigned long long c){
    unsigned long long d;
    asm("fma.rn.f32x2 %0, %1, %2, %3;" : "=l"(d) : "l"(a), "l"(b), "l"(c));
    return d;
}
__device__ __forceinline__ float lo2(unsigned long long a){
    return __uint_as_float((unsigned)(a & 0xffffffffull));
}
__device__ __forceinline__ float hi2(unsigned long long a){
    return __uint_as_float((unsigned)(a >> 32));
}

// ---------------- Eu = mean of emb[su] over all 6144 tokens ----------------
__global__ void k_eu_partial(const int* __restrict__ su, const float* __restrict__ emb){
    __shared__ int sIdx[128];
    int tid = threadIdx.x;
    sIdx[tid] = su[blockIdx.x*128 + tid];
    __syncthreads();
    float sum = 0.f;
    #pragma unroll 4
    for (int t = 0; t < 128; t++)
        sum += emb[(size_t)sIdx[t]*DDIM + tid];
    g_partial[blockIdx.x*DDIM + tid] = sum;
}

__global__ void k_eu_final(){
    int tid = threadIdx.x;
    float s = 0.f;
    #pragma unroll
    for (int b = 0; b < NPART; b++) s += g_partial[b*DDIM + tid];
    g_Eu[tid] = s * (1.0f / (float)NTOK);
}

// ---------------- per-position middle network: one CTA per s ----------------
// The reference's attention block collapses: attn[i,d] == Ec[i,d]
// (softmax rows sum to 1 under the reference's broadcasting), so fc1 input
// is simply [conv(16) | Ec flattened(384)].
__global__ void __launch_bounds__(128) k_mid(
    const int*  __restrict__ su,   const float* __restrict__ emb,
    const float* __restrict__ convK, const float* __restrict__ convb,
    const float* __restrict__ fc1W, const float* __restrict__ fc1b)
{
    const int s   = blockIdx.x;
    const int tid = threadIdx.x;
    const int w   = tid >> 5, lane = tid & 31;

    __shared__ float sIn[NKDIM + LDIM*DDIM];  // fc1 input: [conv(16) | Ec(384)]
    __shared__ float sH[DDIM];
    __shared__ float sMM[4][2];

    float* sEc = sIn + NKDIM;                 // Ec lives directly in fc1 input

    // gather Ec
    #pragma unroll
    for (int l = 0; l < LDIM; l++)
        sEc[l*DDIM + tid] = emb[(size_t)su[s*LDIM + l]*DDIM + tid];
    __syncthreads();

    // VerticalConv: warp w handles kernels k = 4w..4w+3
    #pragma unroll
    for (int kk = 0; kk < 4; kk++){
        int k = w*4 + kk;
        float acc = 0.f;
        #pragma unroll
        for (int j = lane; j < LDIM*DDIM; j += 32)
            acc += sEc[j] * convK[k*(LDIM*DDIM) + j];
        #pragma unroll
        for (int o = 16; o; o >>= 1) acc += __shfl_xor_sync(0xffffffffu, acc, o);
        if (lane == 0) sIn[k] = fmaxf(acc + convb[k], 0.f);
    }
    __syncthreads();

    // fc1: h[e] = relu(fc1b[e] + fc1W[e,:] . sIn)
    float h;
    {
        float acc = fc1b[tid];
        const float4* w4 = (const float4*)(fc1W + (size_t)tid*(NKDIM+LDIM*DDIM));
        #pragma unroll 10
        for (int j4 = 0; j4 < (NKDIM+LDIM*DDIM)/4; j4++){
            float4 a = w4[j4];
            const float* in = sIn + j4*4;
            acc = fmaf(a.x,in[0],fmaf(a.y,in[1],fmaf(a.z,in[2],fmaf(a.w,in[3],acc))));
        }
        h = fmaxf(acc, 0.f);
        sH[tid] = h;
        float mx = h, mn = h;
        #pragma unroll
        for (int o = 16; o; o >>= 1){
            mx = fmaxf(mx, __shfl_xor_sync(0xffffffffu, mx, o));
            mn = fminf(mn, __shfl_xor_sync(0xffffffffu, mn, o));
        }
        if (lane == 0){ sMM[w][0] = mx; sMM[w][1] = mn; }
    }
    __syncthreads();
    float hmax = fmaxf(fmaxf(sMM[0][0],sMM[1][0]), fmaxf(sMM[2][0],sMM[3][0]));
    float hmin = fminf(fminf(sMM[0][1],sMM[1][1]), fminf(sMM[2][1],sMM[3][1]));

    // u_attn[p] = softmax_q(Eu[p]*h[q]) . h    (h >= 0 so max is at hmax/hmin)
    float a = g_Eu[tid];
    float m = (a > 0.f) ? a*hmax : a*hmin;
    float den = 0.f, num = 0.f;
    #pragma unroll 8
    for (int q = 0; q < DDIM; q++){
        float hq = sH[q];
        float t = __expf(fmaf(a, hq, -m));
        den += t;
        num = fmaf(t, hq, num);
    }
    g_usrT[tid*SDIM + s] = num/den;   // transposed store for GEMM A-tile
}

// ---------------- transpose fc2W[:,128:256] -> w2T[k][v] ----------------
__global__ void k_transpose(const float* __restrict__ fc2W){
    __shared__ float tile[32][33];
    int tx = threadIdx.x, ty = threadIdx.y;  // (32, 8)
    int bv = blockIdx.x, bk = blockIdx.y;
    #pragma unroll
    for (int r = 0; r < 4; r++){
        int v = bv*32 + ty + r*8;
        int k = bk*32 + tx;
        tile[ty+r*8][tx] = (v < VOC) ? fc2W[(size_t)v*256 + 128 + k] : 0.f;
    }
    __syncthreads();
    #pragma unroll
    for (int r = 0; r < 4; r++){
        int k = bk*32 + ty + r*8;
        int v = bv*32 + tx;
        if (v < VOC) g_w2T[(size_t)k*VOC + v] = tile[tx][ty+r*8];
    }
}

// ---------------- c[v] = fc2b[v] + Eu . fc2W[v,:128] ----------------
__global__ void k_cvec(const float* __restrict__ fc2W, const float* __restrict__ fc2b){
    __shared__ float sEu[DDIM];
    int tid = threadIdx.x;
    if (tid < DDIM) sEu[tid] = g_Eu[tid];
    __syncthreads();
    int w = tid >> 5, lane = tid & 31;
    int v = blockIdx.x*8 + w;
    float4 ww = *(const float4*)(fc2W + (size_t)v*256 + lane*4);
    float4 ee = *(const float4*)(sEu + lane*4);
    float acc = ww.x*ee.x + ww.y*ee.y + ww.z*ee.z + ww.w*ee.w;
    #pragma unroll
    for (int o = 16; o; o >>= 1) acc += __shfl_xor_sync(0xffffffffu, acc, o);
    if (lane == 0) g_c[v] = acc + fc2b[v];
}

// ---------------- main GEMM: out[s][v] = c[v] + usrT[:,s] . w2T[:,v] ----------------
// CTA tile 128(M) x 256(N), K=128 fully staged. 256 threads.
// Warp grid 2(M) x 4(N) -> warp tile 64x64. Lane grid 8(M) x 4(N) ->
// thread tile 8(M) x 16(N) as 4 strided float4 column chunks (+0,+16,+32,+48).
// All LDS conflict-free; packed f32x2 FMA (2 FMAs/instr).
__global__ void __launch_bounds__(256, 1) k_gemm(float* __restrict__ out){
    extern __shared__ float smem[];
    float* As = smem;                 // [128][128]  (k-major)
    float* Bs = smem + 128*128;       // [128][256]  (k-major)

    const int tid = threadIdx.x;
    const int bm = blockIdx.y * 128;
    const int bn = blockIdx.x * 256;

    // load A tile (coalesced LDG, conflict-free STS)
    #pragma unroll
    for (int p = 0; p < 16; p++){
        int lin = p*256 + tid;            // lin = k*32 + c4
        int k = lin >> 5, c4 = lin & 31;
        ((float4*)As)[lin] = *(const float4*)(g_usrT + (size_t)k*SDIM + bm + c4*4);
    }
    // load B tile (coalesced LDG, conflict-free STS)
    #pragma unroll
    for (int p = 0; p < 32; p++){
        int lin = p*256 + tid;            // lin = k*64 + c4
        int k = lin >> 6, c4 = lin & 63;
        int v = bn + c4*4;
        float4 val = (v < VOC) ? *(const float4*)(g_w2T + (size_t)k*VOC + v)
                               : make_float4(0.f,0.f,0.f,0.f);
        ((float4*)Bs)[lin] = val;
    }
    __syncthreads();

    const int w  = tid >> 5, lane = tid & 31;
    const int wm = w >> 2,  wn = w & 3;       // warp tile origin
    const int lm = lane >> 2, ln = lane & 3;  // lane within warp

    unsigned long long acc[8][8];
    #pragma unroll
    for (int i = 0; i < 8; i++)
        #pragma unroll
        for (int j = 0; j < 8; j++) acc[i][j] = 0ull;

    const float* Ab = As + wm*64 + lm*8;
    const float* Bb = Bs + wn*64 + ln*4;

    #pragma unroll 4
    for (int k = 0; k < 128; k++){
        float4 a0 = *(const float4*)(Ab + k*128);
        float4 a1 = *(const float4*)(Ab + k*128 + 4);
        ulonglong2 b0 = *(const ulonglong2*)(Bb + k*256);
        ulonglong2 b1 = *(const ulonglong2*)(Bb + k*256 + 16);
        ulonglong2 b2 = *(const ulonglong2*)(Bb + k*256 + 32);
        ulonglong2 b3 = *(const ulonglong2*)(Bb + k*256 + 48);
        unsigned long long bb[8] = {b0.x,b0.y,b1.x,b1.y,b2.x,b2.y,b3.x,b3.y};
        float av[8] = {a0.x,a0.y,a0.z,a0.w,a1.x,a1.y,a1.z,a1.w};
        #pragma unroll
        for (int i = 0; i < 8; i++){
            unsigned long long ap = pack2(av[i]);
            #pragma unroll
            for (int j = 0; j < 8; j++)
                acc[i][j] = fma2(ap, bb[j], acc[i][j]);
        }
    }

    // epilogue: add c[v], float4 stores
    #pragma unroll
    for (int i = 0; i < 8; i++){
        int m = bm + wm*64 + lm*8 + i;
        float* orow = out + (size_t)m * VOC;
        #pragma unroll
        for (int c = 0; c < 4; c++){
            int v = bn + wn*64 + ln*4 + c*16;
            if (v < VOC){
                float4 cc = *(const float4*)(g_c + v);
                float4 r;
                r.x = lo2(acc[i][2*c])   + cc.x;
                r.y = hi2(acc[i][2*c])   + cc.y;
                r.z = lo2(acc[i][2*c+1]) + cc.z;
                r.w = hi2(acc[i][2*c+1]) + cc.w;
                *(float4*)(orow + v) = r;
            }
        }
    }
}

// ---------------- launch ----------------
extern "C" void kernel_launch(void* const* d_in, const int* in_sizes, int n_in,
                              void* d_out, int out_size){
    const int*   su    = (const int*)  d_in[0];
    const float* emb   = (const float*)d_in[1];
    const float* convK = (const float*)d_in[2];
    const float* convb = (const float*)d_in[3];
    const float* fc1W  = (const float*)d_in[7];
    const float* fc1b  = (const float*)d_in[8];
    const float* fc2W  = (const float*)d_in[9];
    const float* fc2b  = (const float*)d_in[10];
    float* out = (float*)d_out;

    (void)in_sizes; (void)n_in; (void)out_size;

    cudaFuncSetAttribute(k_gemm, cudaFuncAttributeMaxDynamicSharedMemorySize, 196608);

    k_eu_partial<<<NPART, 128>>>(su, emb);
    k_eu_final<<<1, 128>>>();
    k_mid<<<SDIM, 128>>>(su, emb, convK, convb, fc1W, fc1b);
    k_transpose<<<dim3((VOC+31)/32, DDIM/32), dim3(32, 8)>>>(fc2W);
    k_cvec<<<VOC/8, 256>>>(fc2W, fc2b);
    k_gemm<<<dim3((VOC+255)/256, SDIM/128), 256, 196608>>>(out);
}

// round 6
// speedup vs baseline: 2.6168x; 1.5265x over previous
#include <cuda_runtime.h>
#include <cuda_bf16.h>
#include <cstdint>
#include <math.h>

// Problem constants (fixed shapes)
#define SDIM   2048
#define LDIM   3
#define DDIM   128
#define NKDIM  16
#define VOC    50000
#define NTOK   (SDIM*LDIM)      // 6144
#define NPART  48               // 6144 / 128

// GEMM tiling
#define TILE_M 256
#define TILE_N 128
#define NT_M   8                // 2048/256
#define NT_N   391              // ceil(50000/128) -> padded rows 50048
#define NPADV  (NT_N*128)

// smem layout (bytes): padded rows of 272B (128 bf16 + 16B pad) -> ldmatrix conflict-free
#define ROWB   272
#define A_BUF  (256*ROWB)       // 69632
#define B_BUF  (128*ROWB)       // 34816
#define OFF_A0 0
#define OFF_A1 A_BUF
#define OFF_B0 (2*A_BUF)
#define OFF_B1 (2*A_BUF + B_BUF)
#define SMEM_TOTAL (2*A_BUF + 2*B_BUF)   // 208896

// ---------------- device scratch (static, allocation-free) ----------------
__device__ float g_partial[NPART*DDIM];
__device__ float g_Eu[DDIM];
__device__ float g_c[VOC];                  // c[v] = fc2b[v] + Eu . fc2W[v,:128]
__device__ uint4 g_Ahi4[SDIM*128*2/16];     // u_attn hi  [s][k] bf16
__device__ uint4 g_Alo4[SDIM*128*2/16];     // u_attn lo  [s][k] bf16
__device__ uint4 g_Bhi4[(size_t)NPADV*128*2/16];  // w2 hi [v][k] bf16
__device__ uint4 g_Blo4[(size_t)NPADV*128*2/16];  // w2 lo [v][k] bf16

__device__ __forceinline__ uint32_t smem_u32(const void* p){
    uint32_t a;
    asm("{ .reg .u64 t; cvta.to.shared.u64 t, %1; cvt.u32.u64 %0, t; }" : "=r"(a) : "l"(p));
    return a;
}
__device__ __forceinline__ void cp_async16(uint32_t dst, const void* src){
    asm volatile("cp.async.cg.shared.global [%0], [%1], 16;" :: "r"(dst), "l"(src));
}
#define CP_COMMIT() asm volatile("cp.async.commit_group;" ::: "memory")
#define CP_WAIT(n)  asm volatile("cp.async.wait_group %0;" :: "n"(n) : "memory")

__device__ __forceinline__ void ldsm_x4(uint32_t (&r)[4], uint32_t addr){
    asm volatile("ldmatrix.sync.aligned.m8n8.x4.shared.b16 {%0,%1,%2,%3}, [%4];"
        : "=r"(r[0]), "=r"(r[1]), "=r"(r[2]), "=r"(r[3]) : "r"(addr));
}
__device__ __forceinline__ void mma16816(float (&d)[4], const uint32_t (&a)[4],
                                         uint32_t b0, uint32_t b1){
    asm volatile(
        "mma.sync.aligned.m16n8k16.row.col.f32.bf16.bf16.f32 "
        "{%0,%1,%2,%3}, {%4,%5,%6,%7}, {%8,%9}, {%0,%1,%2,%3};"
        : "+f"(d[0]), "+f"(d[1]), "+f"(d[2]), "+f"(d[3])
        : "r"(a[0]), "r"(a[1]), "r"(a[2]), "r"(a[3]), "r"(b0), "r"(b1));
}
__device__ __forceinline__ unsigned short bf_bits(__nv_bfloat16 h){
    return *reinterpret_cast<unsigned short*>(&h);
}

// ---------------- Eu = mean of emb[su] over all 6144 tokens ----------------
__global__ void k_eu_partial(const int* __restrict__ su, const float* __restrict__ emb){
    __shared__ int sIdx[128];
    int tid = threadIdx.x;
    sIdx[tid] = su[blockIdx.x*128 + tid];
    __syncthreads();
    float sum = 0.f;
    #pragma unroll 4
    for (int t = 0; t < 128; t++)
        sum += emb[(size_t)sIdx[t]*DDIM + tid];
    g_partial[blockIdx.x*DDIM + tid] = sum;
}

__global__ void k_eu_final(){
    int tid = threadIdx.x;
    float s = 0.f;
    #pragma unroll
    for (int b = 0; b < NPART; b++) s += g_partial[b*DDIM + tid];
    g_Eu[tid] = s * (1.0f / (float)NTOK);
}

// ---------------- per-position middle network: one CTA per s ----------------
// Reference attention collapses: attn[i,d] == Ec[i,d] (softmax rows sum to 1
// under the reference broadcasting), so fc1 input = [conv(16) | Ec(384)].
__global__ void __launch_bounds__(128) k_mid(
    const int*  __restrict__ su,   const float* __restrict__ emb,
    const float* __restrict__ convK, const float* __restrict__ convb,
    const float* __restrict__ fc1W, const float* __restrict__ fc1b)
{
    const int s   = blockIdx.x;
    const int tid = threadIdx.x;
    const int w   = tid >> 5, lane = tid & 31;

    __shared__ float sIn[NKDIM + LDIM*DDIM];
    __shared__ float sH[DDIM];
    __shared__ float sMM[4][2];

    float* sEc = sIn + NKDIM;

    #pragma unroll
    for (int l = 0; l < LDIM; l++)
        sEc[l*DDIM + tid] = emb[(size_t)su[s*LDIM + l]*DDIM + tid];
    __syncthreads();

    #pragma unroll
    for (int kk = 0; kk < 4; kk++){
        int k = w*4 + kk;
        float acc = 0.f;
        #pragma unroll
        for (int j = lane; j < LDIM*DDIM; j += 32)
            acc += sEc[j] * convK[k*(LDIM*DDIM) + j];
        #pragma unroll
        for (int o = 16; o; o >>= 1) acc += __shfl_xor_sync(0xffffffffu, acc, o);
        if (lane == 0) sIn[k] = fmaxf(acc + convb[k], 0.f);
    }
    __syncthreads();

    float h;
    {
        float acc = fc1b[tid];
        const float4* w4 = (const float4*)(fc1W + (size_t)tid*(NKDIM+LDIM*DDIM));
        #pragma unroll 10
        for (int j4 = 0; j4 < (NKDIM+LDIM*DDIM)/4; j4++){
            float4 a = w4[j4];
            const float* in = sIn + j4*4;
            acc = fmaf(a.x,in[0],fmaf(a.y,in[1],fmaf(a.z,in[2],fmaf(a.w,in[3],acc))));
        }
        h = fmaxf(acc, 0.f);
        sH[tid] = h;
        float mx = h, mn = h;
        #pragma unroll
        for (int o = 16; o; o >>= 1){
            mx = fmaxf(mx, __shfl_xor_sync(0xffffffffu, mx, o));
            mn = fminf(mn, __shfl_xor_sync(0xffffffffu, mn, o));
        }
        if (lane == 0){ sMM[w][0] = mx; sMM[w][1] = mn; }
    }
    __syncthreads();
    float hmax = fmaxf(fmaxf(sMM[0][0],sMM[1][0]), fmaxf(sMM[2][0],sMM[3][0]));
    float hmin = fminf(fminf(sMM[0][1],sMM[1][1]), fminf(sMM[2][1],sMM[3][1]));

    float a = g_Eu[tid];
    float m = (a > 0.f) ? a*hmax : a*hmin;
    float den = 0.f, num = 0.f;
    #pragma unroll 8
    for (int q = 0; q < DDIM; q++){
        float hq = sH[q];
        float t = __expf(fmaf(a, hq, -m));
        den += t;
        num = fmaf(t, hq, num);
    }
    float u = num/den;

    __nv_bfloat16 hi = __float2bfloat16(u);
    __nv_bfloat16 lo = __float2bfloat16(u - __bfloat162float(hi));
    ((__nv_bfloat16*)g_Ahi4)[s*128 + tid] = hi;
    ((__nv_bfloat16*)g_Alo4)[s*128 + tid] = lo;
}

// ---------------- B prep: fc2W[:,128:256] -> bf16 hi/lo [v][k] ----------------
__global__ void __launch_bounds__(256) k_prepB(const float* __restrict__ fc2W){
    int gid = blockIdx.x*256 + threadIdx.x;      // one thread per (v, 4k)
    int v = gid >> 5, q = gid & 31;
    if (v >= NPADV) return;
    float4 b = (v < VOC) ? *(const float4*)(fc2W + (size_t)v*256 + 128 + q*4)
                         : make_float4(0.f,0.f,0.f,0.f);
    float bb[4] = {b.x, b.y, b.z, b.w};
    unsigned long long hp = 0ull, lp = 0ull;
    #pragma unroll
    for (int i = 0; i < 4; i++){
        __nv_bfloat16 hi = __float2bfloat16(bb[i]);
        __nv_bfloat16 lo = __float2bfloat16(bb[i] - __bfloat162float(hi));
        hp |= (unsigned long long)bf_bits(hi) << (16*i);
        lp |= (unsigned long long)bf_bits(lo) << (16*i);
    }
    ((unsigned long long*)g_Bhi4)[(size_t)v*32 + q] = hp;
    ((unsigned long long*)g_Blo4)[(size_t)v*32 + q] = lp;
}

// ---------------- c[v] = fc2b[v] + Eu . fc2W[v,:128] ----------------
__global__ void k_cvec(const float* __restrict__ fc2W, const float* __restrict__ fc2b){
    __shared__ float sEu[DDIM];
    int tid = threadIdx.x;
    if (tid < DDIM) sEu[tid] = g_Eu[tid];
    __syncthreads();
    int w = tid >> 5, lane = tid & 31;
    int v = blockIdx.x*8 + w;
    float4 ww = *(const float4*)(fc2W + (size_t)v*256 + lane*4);
    float4 ee = *(const float4*)(sEu + lane*4);
    float acc = ww.x*ee.x + ww.y*ee.y + ww.z*ee.z + ww.w*ee.w;
    #pragma unroll
    for (int o = 16; o; o >>= 1) acc += __shfl_xor_sync(0xffffffffu, acc, o);
    if (lane == 0) g_c[v] = acc + fc2b[v];
}

// ---------------- main GEMM via mma.sync bf16, 3-term hi/lo split ----------------
// out[s,v] = c[v] + a_hi.b_hi + a_lo.b_hi + a_hi.b_lo  (f32 accum)
// CTA 256x128, 8 warps (4m x 2n), warp tile 64x64 = 4x8 m16n8k16 frags.
__global__ void __launch_bounds__(256, 1) k_gemm(float* __restrict__ out){
    extern __shared__ char smem[];
    const uint32_t sb = smem_u32(smem);
    const int t = threadIdx.x;
    const int bm = blockIdx.x * TILE_M;
    const int bn = blockIdx.y * TILE_N;

    // stage loads: A rows 256B in gmem -> 272B rows in smem
    const char* gAhi = (const char*)g_Ahi4 + (size_t)bm*256;
    const char* gAlo = (const char*)g_Alo4 + (size_t)bm*256;
    const char* gBhi = (const char*)g_Bhi4 + (size_t)bn*256;
    const char* gBlo = (const char*)g_Blo4 + (size_t)bn*256;

    #pragma unroll
    for (int i = 0; i < 16; i++){
        int idx = i*256 + t, r = idx >> 4, c = idx & 15;
        cp_async16(sb + OFF_A0 + r*ROWB + c*16, gAhi + (size_t)r*256 + c*16);
    }
    #pragma unroll
    for (int i = 0; i < 8; i++){
        int idx = i*256 + t, r = idx >> 4, c = idx & 15;
        cp_async16(sb + OFF_B0 + r*ROWB + c*16, gBhi + (size_t)r*256 + c*16);
    }
    CP_COMMIT();
    #pragma unroll
    for (int i = 0; i < 16; i++){
        int idx = i*256 + t, r = idx >> 4, c = idx & 15;
        cp_async16(sb + OFF_A1 + r*ROWB + c*16, gAlo + (size_t)r*256 + c*16);
    }
    #pragma unroll
    for (int i = 0; i < 8; i++){
        int idx = i*256 + t, r = idx >> 4, c = idx & 15;
        cp_async16(sb + OFF_B1 + r*ROWB + c*16, gBlo + (size_t)r*256 + c*16);
    }
    CP_COMMIT();

    const int lane = t & 31, wid = t >> 5;
    const int wm = wid >> 1, wn = wid & 1;
    const uint32_t lmo = (uint32_t)((lane & 15)*ROWB + (lane >> 4)*16);

    float acc[4][8][4];
    #pragma unroll
    for (int mi = 0; mi < 4; mi++)
        #pragma unroll
        for (int nt = 0; nt < 8; nt++)
            #pragma unroll
            for (int q = 0; q < 4; q++) acc[mi][nt][q] = 0.f;

    const uint32_t aW = (uint32_t)(wm*64*ROWB);
    const uint32_t bW = (uint32_t)(wn*64*ROWB);

    #define DO_PASS(OFFA, OFFB) do { \
        uint32_t aBase = sb + (OFFA) + aW + lmo; \
        uint32_t bBase = sb + (OFFB) + bW + lmo; \
        _Pragma("unroll") \
        for (int ks = 0; ks < 8; ks++){ \
            uint32_t ua[4][4], ub[4][4]; \
            _Pragma("unroll") \
            for (int mi = 0; mi < 4; mi++) \
                ldsm_x4(ua[mi], aBase + mi*16*ROWB + ks*32); \
            _Pragma("unroll") \
            for (int nj = 0; nj < 4; nj++) \
                ldsm_x4(ub[nj], bBase + nj*16*ROWB + ks*32); \
            _Pragma("unroll") \
            for (int mi = 0; mi < 4; mi++) \
                _Pragma("unroll") \
                for (int nt = 0; nt < 8; nt++) \
                    mma16816(acc[mi][nt], ua[mi], \
                             ub[nt>>1][nt&1], ub[nt>>1][2+(nt&1)]); \
        } } while(0)

    CP_WAIT(1);
    __syncthreads();
    DO_PASS(OFF_A0, OFF_B0);     // a_hi . b_hi
    CP_WAIT(0);
    __syncthreads();
    DO_PASS(OFF_A1, OFF_B0);     // a_lo . b_hi
    DO_PASS(OFF_A0, OFF_B1);     // a_hi . b_lo

    // epilogue: add c[v], write float2 pairs
    const int gID = lane >> 2, tig = lane & 3;
    #pragma unroll
    for (int nt = 0; nt < 8; nt++){
        int v = bn + wn*64 + nt*8 + tig*2;
        if (v >= VOC) continue;
        float2 cc = *(const float2*)(g_c + v);
        #pragma unroll
        for (int mi = 0; mi < 4; mi++){
            int r0 = bm + wm*64 + mi*16 + gID;
            float2 d0 = { acc[mi][nt][0] + cc.x, acc[mi][nt][1] + cc.y };
            float2 d1 = { acc[mi][nt][2] + cc.x, acc[mi][nt][3] + cc.y };
            *(float2*)(out + (size_t)r0*VOC + v)       = d0;
            *(float2*)(out + (size_t)(r0+8)*VOC + v)   = d1;
        }
    }
    #undef DO_PASS
}

// ---------------- launch ----------------
extern "C" void kernel_launch(void* const* d_in, const int* in_sizes, int n_in,
                              void* d_out, int out_size){
    const int*   su    = (const int*)  d_in[0];
    const float* emb   = (const float*)d_in[1];
    const float* convK = (const float*)d_in[2];
    const float* convb = (const float*)d_in[3];
    const float* fc1W  = (const float*)d_in[7];
    const float* fc1b  = (const float*)d_in[8];
    const float* fc2W  = (const float*)d_in[9];
    const float* fc2b  = (const float*)d_in[10];
    float* out = (float*)d_out;

    (void)in_sizes; (void)n_in; (void)out_size;

    cudaFuncSetAttribute(k_gemm, cudaFuncAttributeMaxDynamicSharedMemorySize, SMEM_TOTAL);

    k_eu_partial<<<NPART, 128>>>(su, emb);
    k_eu_final<<<1, 128>>>();
    k_mid<<<SDIM, 128>>>(su, emb, convK, convb, fc1W, fc1b);
    k_prepB<<<(NPADV*32 + 255)/256, 256>>>(fc2W);
    k_cvec<<<VOC/8, 256>>>(fc2W, fc2b);
    // grid.x = M tiles (innermost) so each wave reuses B tiles across M
    k_gemm<<<dim3(NT_M, NT_N), 256, SMEM_TOTAL>>>(out);
}

// round 7
// speedup vs baseline: 3.0273x; 1.1569x over previous
#include <cuda_runtime.h>
#include <cuda_bf16.h>
#include <cstdint>
#include <math.h>

// Problem constants (fixed shapes)
#define SDIM   2048
#define LDIM   3
#define DDIM   128
#define NKDIM  16
#define VOC    50000
#define NTOK   (SDIM*LDIM)      // 6144
#define NPART  48               // 6144 / 128

// GEMM config: persistent CTAs, M-stripe resident, B streamed in 64-col tiles
#define GT_N    64
#define N_NT    782             // 50048 / 64
#define NPADV   (N_NT*GT_N)     // 50048
#define NSLOT   18              // B-tile slots -> 8 M * 18 = 144 CTAs
#define ROWB    272             // 256B row + 16B pad (ldmatrix conflict-free)
#define A_SZ    (256*ROWB)      // 69632 (one of hi/lo)
#define B_SZ    (GT_N*ROWB)     // 17408 (one of hi/lo)
#define OFF_A0  0
#define OFF_A1  A_SZ
#define OFF_B   (2*A_SZ)        // two buffers of (hi|lo) = 2*2*B_SZ
#define SMEM_TOTAL (2*A_SZ + 4*B_SZ)   // 208896

// k_mid batching
#define MPOS  8
#define FCIN  (NKDIM + LDIM*DDIM)   // 400

// ---------------- device scratch (static, allocation-free) ----------------
__device__ float g_partial[NPART*DDIM];
__device__ float g_Eu[DDIM];
__device__ float g_c[VOC];                  // c[v] = fc2b[v] + Eu . fc2W[v,:128]
__device__ uint4 g_Ahi4[SDIM*128*2/16];     // u_attn hi  [s][k] bf16
__device__ uint4 g_Alo4[SDIM*128*2/16];     // u_attn lo  [s][k] bf16
__device__ uint4 g_Bhi4[(size_t)NPADV*128*2/16];  // w2 hi [v][k] bf16
__device__ uint4 g_Blo4[(size_t)NPADV*128*2/16];  // w2 lo [v][k] bf16

__device__ __forceinline__ uint32_t smem_u32(const void* p){
    uint32_t a;
    asm("{ .reg .u64 t; cvta.to.shared.u64 t, %1; cvt.u32.u64 %0, t; }" : "=r"(a) : "l"(p));
    return a;
}
__device__ __forceinline__ void cp_async16(uint32_t dst, const void* src){
    asm volatile("cp.async.cg.shared.global [%0], [%1], 16;" :: "r"(dst), "l"(src));
}
#define CP_COMMIT() asm volatile("cp.async.commit_group;" ::: "memory")
#define CP_WAIT(n)  asm volatile("cp.async.wait_group %0;" :: "n"(n) : "memory")

__device__ __forceinline__ void ldsm_x4(uint32_t (&r)[4], uint32_t addr){
    asm volatile("ldmatrix.sync.aligned.m8n8.x4.shared.b16 {%0,%1,%2,%3}, [%4];"
        : "=r"(r[0]), "=r"(r[1]), "=r"(r[2]), "=r"(r[3]) : "r"(addr));
}
__device__ __forceinline__ void mma16816(float (&d)[4], const uint32_t (&a)[4],
                                         uint32_t b0, uint32_t b1){
    asm volatile(
        "mma.sync.aligned.m16n8k16.row.col.f32.bf16.bf16.f32 "
        "{%0,%1,%2,%3}, {%4,%5,%6,%7}, {%8,%9}, {%0,%1,%2,%3};"
        : "+f"(d[0]), "+f"(d[1]), "+f"(d[2]), "+f"(d[3])
        : "r"(a[0]), "r"(a[1]), "r"(a[2]), "r"(a[3]), "r"(b0), "r"(b1));
}
__device__ __forceinline__ unsigned short bf_bits(__nv_bfloat16 h){
    return *reinterpret_cast<unsigned short*>(&h);
}

// ---------------- Eu = mean of emb[su] over all 6144 tokens ----------------
__global__ void k_eu_partial(const int* __restrict__ su, const float* __restrict__ emb){
    __shared__ int sIdx[128];
    int tid = threadIdx.x;
    sIdx[tid] = su[blockIdx.x*128 + tid];
    __syncthreads();
    float sum = 0.f;
    #pragma unroll 4
    for (int t = 0; t < 128; t++)
        sum += emb[(size_t)sIdx[t]*DDIM + tid];
    g_partial[blockIdx.x*DDIM + tid] = sum;
}

__global__ void k_eu_final(){
    int tid = threadIdx.x;
    float s = 0.f;
    #pragma unroll
    for (int b = 0; b < NPART; b++) s += g_partial[b*DDIM + tid];
    g_Eu[tid] = s * (1.0f / (float)NTOK);
}

// ---------------- middle network: 8 positions per CTA ----------------
// Reference attention collapses: attn[i,d] == Ec[i,d] (softmax rows sum to 1
// under the reference broadcasting), so fc1 input = [conv(16) | Ec(384)].
__global__ void __launch_bounds__(128) k_mid(
    const int*  __restrict__ su,   const float* __restrict__ emb,
    const float* __restrict__ convK, const float* __restrict__ convb,
    const float* __restrict__ fc1W, const float* __restrict__ fc1b)
{
    const int bx  = blockIdx.x;           // 256 CTAs, positions bx*8 .. bx*8+7
    const int tid = threadIdx.x;
    const int w   = tid >> 5, lane = tid & 31;

    __shared__ float sIn[MPOS][FCIN];     // [conv(16) | Ec(384)] per position
    __shared__ float sH[MPOS][DDIM];
    __shared__ float sMM[4][MPOS][2];

    // gather Ec for 8 positions
    #pragma unroll
    for (int p = 0; p < MPOS; p++){
        int s = bx*MPOS + p;
        #pragma unroll
        for (int l = 0; l < LDIM; l++)
            sIn[p][NKDIM + l*DDIM + tid] = emb[(size_t)su[s*LDIM + l]*DDIM + tid];
    }
    __syncthreads();

    // conv: warp w owns kernels 4w..4w+3; conv weights cached in regs, reused x8
    #pragma unroll
    for (int kk = 0; kk < 4; kk++){
        int k = w*4 + kk;
        float ck[12];
        #pragma unroll
        for (int j = 0; j < 12; j++) ck[j] = convK[k*(LDIM*DDIM) + lane + j*32];
        float cb = convb[k];
        #pragma unroll
        for (int p = 0; p < MPOS; p++){
            float acc = 0.f;
            #pragma unroll
            for (int j = 0; j < 12; j++)
                acc += ck[j] * sIn[p][NKDIM + lane + j*32];
            #pragma unroll
            for (int o = 16; o; o >>= 1) acc += __shfl_xor_sync(0xffffffffu, acc, o);
            if (lane == 0) sIn[p][k] = fmaxf(acc + cb, 0.f);
        }
    }
    __syncthreads();

    // fc1: thread e reads its weight row once, applies to all 8 positions
    float acc[MPOS];
    {
        float bias = fc1b[tid];
        #pragma unroll
        for (int p = 0; p < MPOS; p++) acc[p] = bias;
        const float4* w4 = (const float4*)(fc1W + (size_t)tid*FCIN);
        #pragma unroll 4
        for (int j4 = 0; j4 < FCIN/4; j4++){
            float4 a = w4[j4];
            #pragma unroll
            for (int p = 0; p < MPOS; p++){
                float4 in = *(const float4*)&sIn[p][j4*4];
                acc[p] = fmaf(a.x,in.x,fmaf(a.y,in.y,fmaf(a.z,in.z,fmaf(a.w,in.w,acc[p]))));
            }
        }
    }
    #pragma unroll
    for (int p = 0; p < MPOS; p++){
        float h = fmaxf(acc[p], 0.f);
        sH[p][tid] = h;
        float mx = h, mn = h;
        #pragma unroll
        for (int o = 16; o; o >>= 1){
            mx = fmaxf(mx, __shfl_xor_sync(0xffffffffu, mx, o));
            mn = fminf(mn, __shfl_xor_sync(0xffffffffu, mn, o));
        }
        if (lane == 0){ sMM[w][p][0] = mx; sMM[w][p][1] = mn; }
    }
    __syncthreads();

    // u_attn softmax per position; write bf16 hi/lo A rows
    float a = g_Eu[tid];
    #pragma unroll
    for (int p = 0; p < MPOS; p++){
        float hmax = fmaxf(fmaxf(sMM[0][p][0],sMM[1][p][0]), fmaxf(sMM[2][p][0],sMM[3][p][0]));
        float hmin = fminf(fminf(sMM[0][p][1],sMM[1][p][1]), fminf(sMM[2][p][1],sMM[3][p][1]));
        float m = (a > 0.f) ? a*hmax : a*hmin;
        float den = 0.f, num = 0.f;
        #pragma unroll 8
        for (int q = 0; q < DDIM; q++){
            float hq = sH[p][q];
            float t = __expf(fmaf(a, hq, -m));
            den += t;
            num = fmaf(t, hq, num);
        }
        float u = num/den;
        __nv_bfloat16 hi = __float2bfloat16(u);
        __nv_bfloat16 lo = __float2bfloat16(u - __bfloat162float(hi));
        int s = bx*MPOS + p;
        ((__nv_bfloat16*)g_Ahi4)[s*128 + tid] = hi;
        ((__nv_bfloat16*)g_Alo4)[s*128 + tid] = lo;
    }
}

// ---------------- B prep: fc2W[:,128:256] -> bf16 hi/lo [v][k] ----------------
__global__ void __launch_bounds__(256) k_prepB(const float* __restrict__ fc2W){
    int gid = blockIdx.x*256 + threadIdx.x;      // one thread per (v, 4k)
    int v = gid >> 5, q = gid & 31;
    if (v >= NPADV) return;
    float4 b = (v < VOC) ? *(const float4*)(fc2W + (size_t)v*256 + 128 + q*4)
                         : make_float4(0.f,0.f,0.f,0.f);
    float bb[4] = {b.x, b.y, b.z, b.w};
    unsigned long long hp = 0ull, lp = 0ull;
    #pragma unroll
    for (int i = 0; i < 4; i++){
        __nv_bfloat16 hi = __float2bfloat16(bb[i]);
        __nv_bfloat16 lo = __float2bfloat16(bb[i] - __bfloat162float(hi));
        hp |= (unsigned long long)bf_bits(hi) << (16*i);
        lp |= (unsigned long long)bf_bits(lo) << (16*i);
    }
    ((unsigned long long*)g_Bhi4)[(size_t)v*32 + q] = hp;
    ((unsigned long long*)g_Blo4)[(size_t)v*32 + q] = lp;
}

// ---------------- c[v] = fc2b[v] + Eu . fc2W[v,:128] ----------------
__global__ void k_cvec(const float* __restrict__ fc2W, const float* __restrict__ fc2b){
    __shared__ float sEu[DDIM];
    int tid = threadIdx.x;
    if (tid < DDIM) sEu[tid] = g_Eu[tid];
    __syncthreads();
    int w = tid >> 5, lane = tid & 31;
    int v = blockIdx.x*8 + w;
    float4 ww = *(const float4*)(fc2W + (size_t)v*256 + lane*4);
    float4 ee = *(const float4*)(sEu + lane*4);
    float acc = ww.x*ee.x + ww.y*ee.y + ww.z*ee.z + ww.w*ee.w;
    #pragma unroll
    for (int o = 16; o; o >>= 1) acc += __shfl_xor_sync(0xffffffffu, acc, o);
    if (lane == 0) g_c[v] = acc + fc2b[v];
}

// ---------------- persistent GEMM ----------------
// out[s,v] = c[v] + a_hi.b_hi + a_lo.b_hi + a_hi.b_lo  (f32 accum, mma.sync bf16)
// grid (NSLOT, 8): blockIdx.y = M-stripe (256 rows, A resident in SMEM),
// blockIdx.x = N slot; CTA walks n-tiles bx, bx+18, ... double-buffered cp.async.
__global__ void __launch_bounds__(256, 1) k_gemm(float* __restrict__ out){
    extern __shared__ char smem[];
    const uint32_t sb = smem_u32(smem);
    const int t = threadIdx.x;
    const int m_base = blockIdx.y * 256;

    // resident A loads (hi & lo)
    {
        const char* gAhi = (const char*)g_Ahi4 + (size_t)m_base*256;
        const char* gAlo = (const char*)g_Alo4 + (size_t)m_base*256;
        #pragma unroll
        for (int i = 0; i < 16; i++){
            int idx = i*256 + t, r = idx >> 4, c = idx & 15;
            cp_async16(sb + OFF_A0 + r*ROWB + c*16, gAhi + (size_t)idx*16);
            cp_async16(sb + OFF_A1 + r*ROWB + c*16, gAlo + (size_t)idx*16);
        }
    }
    // first B tile into buffer 0
    int nt = blockIdx.x;
    {
        const char* gh = (const char*)g_Bhi4 + (size_t)nt*GT_N*256;
        const char* gl = (const char*)g_Blo4 + (size_t)nt*GT_N*256;
        #pragma unroll
        for (int i = 0; i < 4; i++){
            int idx = i*256 + t, r = idx >> 4, c = idx & 15;
            cp_async16(sb + OFF_B + r*ROWB + c*16,        gh + (size_t)idx*16);
            cp_async16(sb + OFF_B + B_SZ + r*ROWB + c*16, gl + (size_t)idx*16);
        }
    }
    CP_COMMIT();
    CP_WAIT(0);
    __syncthreads();

    const int lane = t & 31, wid = t >> 5;
    const int wm = wid >> 1, wn = wid & 1;            // 4 x 2 warps -> 64x32 tiles
    const uint32_t lmo = (uint32_t)((lane & 15)*ROWB + (lane >> 4)*16);
    const uint32_t aW = (uint32_t)(wm*64*ROWB);
    const uint32_t bW = (uint32_t)(wn*32*ROWB);
    const int gID = lane >> 2, tig = lane & 3;

    int cur = 0;
    while (nt < N_NT){
        int nnt = nt + NSLOT;
        if (nnt < N_NT){
            uint32_t dst = sb + OFF_B + (uint32_t)((cur^1)*2*B_SZ);
            const char* gh = (const char*)g_Bhi4 + (size_t)nnt*GT_N*256;
            const char* gl = (const char*)g_Blo4 + (size_t)nnt*GT_N*256;
            #pragma unroll
            for (int i = 0; i < 4; i++){
                int idx = i*256 + t, r = idx >> 4, c = idx & 15;
                cp_async16(dst + r*ROWB + c*16,        gh + (size_t)idx*16);
                cp_async16(dst + B_SZ + r*ROWB + c*16, gl + (size_t)idx*16);
            }
        }
        CP_COMMIT();

        float acc[4][4][4];
        #pragma unroll
        for (int mi = 0; mi < 4; mi++)
            #pragma unroll
            for (int n8 = 0; n8 < 4; n8++)
                #pragma unroll
                for (int q = 0; q < 4; q++) acc[mi][n8][q] = 0.f;

        const uint32_t bb = sb + OFF_B + (uint32_t)(cur*2*B_SZ);

        #define DO_PASS(ABASE, BBASE) do { \
            uint32_t aB = (ABASE) + aW + lmo; \
            uint32_t bB = (BBASE) + bW + lmo; \
            _Pragma("unroll") \
            for (int ks = 0; ks < 8; ks++){ \
                uint32_t ua[4][4], ub[2][4]; \
                _Pragma("unroll") \
                for (int mi = 0; mi < 4; mi++) \
                    ldsm_x4(ua[mi], aB + mi*16*ROWB + ks*32); \
                _Pragma("unroll") \
                for (int nj = 0; nj < 2; nj++) \
                    ldsm_x4(ub[nj], bB + nj*16*ROWB + ks*32); \
                _Pragma("unroll") \
                for (int mi = 0; mi < 4; mi++) \
                    _Pragma("unroll") \
                    for (int n8 = 0; n8 < 4; n8++) \
                        mma16816(acc[mi][n8], ua[mi], \
                                 ub[n8>>1][n8&1], ub[n8>>1][2+(n8&1)]); \
            } } while(0)

        DO_PASS(sb + OFF_A0, bb);            // a_hi . b_hi
        DO_PASS(sb + OFF_A1, bb);            // a_lo . b_hi
        DO_PASS(sb + OFF_A0, bb + B_SZ);     // a_hi . b_lo
        #undef DO_PASS

        // epilogue
        #pragma unroll
        for (int n8 = 0; n8 < 4; n8++){
            int v = nt*GT_N + wn*32 + n8*8 + tig*2;
            if (v < VOC){
                float2 cc = *(const float2*)(g_c + v);
                #pragma unroll
                for (int mi = 0; mi < 4; mi++){
                    int r0 = m_base + wm*64 + mi*16 + gID;
                    float2 d0 = { acc[mi][n8][0] + cc.x, acc[mi][n8][1] + cc.y };
                    float2 d1 = { acc[mi][n8][2] + cc.x, acc[mi][n8][3] + cc.y };
                    *(float2*)(out + (size_t)r0*VOC + v)     = d0;
                    *(float2*)(out + (size_t)(r0+8)*VOC + v) = d1;
                }
            }
        }

        CP_WAIT(0);
        __syncthreads();
        cur ^= 1;
        nt = nnt;
    }
}

// ---------------- launch ----------------
extern "C" void kernel_launch(void* const* d_in, const int* in_sizes, int n_in,
                              void* d_out, int out_size){
    const int*   su    = (const int*)  d_in[0];
    const float* emb   = (const float*)d_in[1];
    const float* convK = (const float*)d_in[2];
    const float* convb = (const float*)d_in[3];
    const float* fc1W  = (const float*)d_in[7];
    const float* fc1b  = (const float*)d_in[8];
    const float* fc2W  = (const float*)d_in[9];
    const float* fc2b  = (const float*)d_in[10];
    float* out = (float*)d_out;

    (void)in_sizes; (void)n_in; (void)out_size;

    cudaFuncSetAttribute(k_gemm, cudaFuncAttributeMaxDynamicSharedMemorySize, SMEM_TOTAL);

    k_eu_partial<<<NPART, 128>>>(su, emb);
    k_eu_final<<<1, 128>>>();
    k_mid<<<SDIM/MPOS, 128>>>(su, emb, convK, convb, fc1W, fc1b);
    k_prepB<<<(NPADV*32 + 255)/256, 256>>>(fc2W);
    k_cvec<<<VOC/8, 256>>>(fc2W, fc2b);
    k_gemm<<<dim3(NSLOT, 8), 256, SMEM_TOTAL>>>(out);
}

// round 8
// speedup vs baseline: 3.0300x; 1.0009x over previous
#include <cuda_runtime.h>
#include <cuda_bf16.h>
#include <cstdint>
#include <math.h>

// Problem constants (fixed shapes)
#define SDIM   2048
#define LDIM   3
#define DDIM   128
#define NKDIM  16
#define VOC    50000
#define NTOK   (SDIM*LDIM)      // 6144
#define NPART  48               // 6144 / 128

// GEMM config: persistent CTAs, M-stripe resident, B streamed in 64-col tiles
#define GT_N    64
#define N_NT    782             // 50048 / 64
#define NPADV   (N_NT*GT_N)     // 50048
#define NSLOT   18              // B-tile slots -> 8 M * 18 = 144 CTAs
#define ROWB    272             // 256B row + 16B pad (ldmatrix conflict-free)
#define A_SZ    (256*ROWB)      // 69632 (one of hi/lo)
#define B_SZ    (GT_N*ROWB)     // 17408 (one of hi/lo)
#define OFF_A0  0
#define OFF_A1  A_SZ
#define OFF_B   (2*A_SZ)        // two buffers of (hi|lo) = 2*2*B_SZ
#define SMEM_TOTAL (2*A_SZ + 4*B_SZ)   // 208896

// k_mid batching
#define MPOS  8
#define FCIN  (NKDIM + LDIM*DDIM)   // 400

// ---------------- device scratch (static, allocation-free) ----------------
__device__ float g_partial[NPART*DDIM];
__device__ float g_Eu[DDIM];
__device__ float g_c[VOC];                  // c[v] = fc2b[v] + Eu . fc2W[v,:128]
__device__ uint4 g_Ahi4[SDIM*128*2/16];     // u_attn hi  [s][k] bf16
__device__ uint4 g_Alo4[SDIM*128*2/16];     // u_attn lo  [s][k] bf16
__device__ uint4 g_Bhi4[(size_t)NPADV*128*2/16];  // w2 hi [v][k] bf16
__device__ uint4 g_Blo4[(size_t)NPADV*128*2/16];  // w2 lo [v][k] bf16

__device__ __forceinline__ uint32_t smem_u32(const void* p){
    uint32_t a;
    asm("{ .reg .u64 t; cvta.to.shared.u64 t, %1; cvt.u32.u64 %0, t; }" : "=r"(a) : "l"(p));
    return a;
}
__device__ __forceinline__ void cp_async16(uint32_t dst, const void* src){
    asm volatile("cp.async.cg.shared.global [%0], [%1], 16;" :: "r"(dst), "l"(src));
}
#define CP_COMMIT() asm volatile("cp.async.commit_group;" ::: "memory")
#define CP_WAIT(n)  asm volatile("cp.async.wait_group %0;" :: "n"(n) : "memory")

__device__ __forceinline__ void ldsm_x4(uint32_t (&r)[4], uint32_t addr){
    asm volatile("ldmatrix.sync.aligned.m8n8.x4.shared.b16 {%0,%1,%2,%3}, [%4];"
        : "=r"(r[0]), "=r"(r[1]), "=r"(r[2]), "=r"(r[3]) : "r"(addr));
}
__device__ __forceinline__ void mma16816(float (&d)[4], const uint32_t (&a)[4],
                                         uint32_t b0, uint32_t b1){
    asm volatile(
        "mma.sync.aligned.m16n8k16.row.col.f32.bf16.bf16.f32 "
        "{%0,%1,%2,%3}, {%4,%5,%6,%7}, {%8,%9}, {%0,%1,%2,%3};"
        : "+f"(d[0]), "+f"(d[1]), "+f"(d[2]), "+f"(d[3])
        : "r"(a[0]), "r"(a[1]), "r"(a[2]), "r"(a[3]), "r"(b0), "r"(b1));
}
__device__ __forceinline__ unsigned short bf_bits(__nv_bfloat16 h){
    return *reinterpret_cast<unsigned short*>(&h);
}

// ---------------- Eu = mean of emb[su] over all 6144 tokens ----------------
__global__ void k_eu_partial(const int* __restrict__ su, const float* __restrict__ emb){
    __shared__ int sIdx[128];
    int tid = threadIdx.x;
    sIdx[tid] = su[blockIdx.x*128 + tid];
    __syncthreads();
    float sum = 0.f;
    #pragma unroll 4
    for (int t = 0; t < 128; t++)
        sum += emb[(size_t)sIdx[t]*DDIM + tid];
    g_partial[blockIdx.x*DDIM + tid] = sum;
}

__global__ void k_eu_final(){
    int tid = threadIdx.x;
    float s = 0.f;
    #pragma unroll
    for (int b = 0; b < NPART; b++) s += g_partial[b*DDIM + tid];
    g_Eu[tid] = s * (1.0f / (float)NTOK);
}

// ---------------- middle network: 8 positions per CTA ----------------
// Reference attention collapses: attn[i,d] == Ec[i,d] (softmax rows sum to 1
// under the reference broadcasting), so fc1 input = [conv(16) | Ec(384)].
__global__ void __launch_bounds__(128) k_mid(
    const int*  __restrict__ su,   const float* __restrict__ emb,
    const float* __restrict__ convK, const float* __restrict__ convb,
    const float* __restrict__ fc1W, const float* __restrict__ fc1b)
{
    const int bx  = blockIdx.x;           // 256 CTAs, positions bx*8 .. bx*8+7
    const int tid = threadIdx.x;
    const int w   = tid >> 5, lane = tid & 31;

    __shared__ float sIn[MPOS][FCIN];     // [conv(16) | Ec(384)] per position
    __shared__ float sH[MPOS][DDIM];
    __shared__ float sMM[4][MPOS][2];

    // gather Ec for 8 positions
    #pragma unroll
    for (int p = 0; p < MPOS; p++){
        int s = bx*MPOS + p;
        #pragma unroll
        for (int l = 0; l < LDIM; l++)
            sIn[p][NKDIM + l*DDIM + tid] = emb[(size_t)su[s*LDIM + l]*DDIM + tid];
    }
    __syncthreads();

    // conv: warp w owns kernels 4w..4w+3; conv weights cached in regs, reused x8
    #pragma unroll
    for (int kk = 0; kk < 4; kk++){
        int k = w*4 + kk;
        float ck[12];
        #pragma unroll
        for (int j = 0; j < 12; j++) ck[j] = convK[k*(LDIM*DDIM) + lane + j*32];
        float cb = convb[k];
        #pragma unroll
        for (int p = 0; p < MPOS; p++){
            float acc = 0.f;
            #pragma unroll
            for (int j = 0; j < 12; j++)
                acc += ck[j] * sIn[p][NKDIM + lane + j*32];
            #pragma unroll
            for (int o = 16; o; o >>= 1) acc += __shfl_xor_sync(0xffffffffu, acc, o);
            if (lane == 0) sIn[p][k] = fmaxf(acc + cb, 0.f);
        }
    }
    __syncthreads();

    // fc1: thread e reads its weight row once, applies to all 8 positions
    float acc[MPOS];
    {
        float bias = fc1b[tid];
        #pragma unroll
        for (int p = 0; p < MPOS; p++) acc[p] = bias;
        const float4* w4 = (const float4*)(fc1W + (size_t)tid*FCIN);
        #pragma unroll 4
        for (int j4 = 0; j4 < FCIN/4; j4++){
            float4 a = w4[j4];
            #pragma unroll
            for (int p = 0; p < MPOS; p++){
                float4 in = *(const float4*)&sIn[p][j4*4];
                acc[p] = fmaf(a.x,in.x,fmaf(a.y,in.y,fmaf(a.z,in.z,fmaf(a.w,in.w,acc[p]))));
            }
        }
    }
    #pragma unroll
    for (int p = 0; p < MPOS; p++){
        float h = fmaxf(acc[p], 0.f);
        sH[p][tid] = h;
        float mx = h, mn = h;
        #pragma unroll
        for (int o = 16; o; o >>= 1){
            mx = fmaxf(mx, __shfl_xor_sync(0xffffffffu, mx, o));
            mn = fminf(mn, __shfl_xor_sync(0xffffffffu, mn, o));
        }
        if (lane == 0){ sMM[w][p][0] = mx; sMM[w][p][1] = mn; }
    }
    __syncthreads();

    // u_attn softmax per position; write bf16 hi/lo A rows
    float a = g_Eu[tid];
    #pragma unroll
    for (int p = 0; p < MPOS; p++){
        float hmax = fmaxf(fmaxf(sMM[0][p][0],sMM[1][p][0]), fmaxf(sMM[2][p][0],sMM[3][p][0]));
        float hmin = fminf(fminf(sMM[0][p][1],sMM[1][p][1]), fminf(sMM[2][p][1],sMM[3][p][1]));
        float m = (a > 0.f) ? a*hmax : a*hmin;
        float den = 0.f, num = 0.f;
        #pragma unroll 8
        for (int q = 0; q < DDIM; q++){
            float hq = sH[p][q];
            float t = __expf(fmaf(a, hq, -m));
            den += t;
            num = fmaf(t, hq, num);
        }
        float u = num/den;
        __nv_bfloat16 hi = __float2bfloat16(u);
        __nv_bfloat16 lo = __float2bfloat16(u - __bfloat162float(hi));
        int s = bx*MPOS + p;
        ((__nv_bfloat16*)g_Ahi4)[s*128 + tid] = hi;
        ((__nv_bfloat16*)g_Alo4)[s*128 + tid] = lo;
    }
}

// ---------------- B prep: fc2W[:,128:256] -> bf16 hi/lo [v][k] ----------------
__global__ void __launch_bounds__(256) k_prepB(const float* __restrict__ fc2W){
    int gid = blockIdx.x*256 + threadIdx.x;      // one thread per (v, 4k)
    int v = gid >> 5, q = gid & 31;
    if (v >= NPADV) return;
    float4 b = (v < VOC) ? *(const float4*)(fc2W + (size_t)v*256 + 128 + q*4)
                         : make_float4(0.f,0.f,0.f,0.f);
    float bb[4] = {b.x, b.y, b.z, b.w};
    unsigned long long hp = 0ull, lp = 0ull;
    #pragma unroll
    for (int i = 0; i < 4; i++){
        __nv_bfloat16 hi = __float2bfloat16(bb[i]);
        __nv_bfloat16 lo = __float2bfloat16(bb[i] - __bfloat162float(hi));
        hp |= (unsigned long long)bf_bits(hi) << (16*i);
        lp |= (unsigned long long)bf_bits(lo) << (16*i);
    }
    ((unsigned long long*)g_Bhi4)[(size_t)v*32 + q] = hp;
    ((unsigned long long*)g_Blo4)[(size_t)v*32 + q] = lp;
}

// ---------------- c[v] = fc2b[v] + Eu . fc2W[v,:128] ----------------
__global__ void k_cvec(const float* __restrict__ fc2W, const float* __restrict__ fc2b){
    __shared__ float sEu[DDIM];
    int tid = threadIdx.x;
    if (tid < DDIM) sEu[tid] = g_Eu[tid];
    __syncthreads();
    int w = tid >> 5, lane = tid & 31;
    int v = blockIdx.x*8 + w;
    float4 ww = *(const float4*)(fc2W + (size_t)v*256 + lane*4);
    float4 ee = *(const float4*)(sEu + lane*4);
    float acc = ww.x*ee.x + ww.y*ee.y + ww.z*ee.z + ww.w*ee.w;
    #pragma unroll
    for (int o = 16; o; o >>= 1) acc += __shfl_xor_sync(0xffffffffu, acc, o);
    if (lane == 0) g_c[v] = acc + fc2b[v];
}

// ---------------- persistent GEMM ----------------
// out[s,v] = c[v] + a_hi.b_hi + a_lo.b_hi + a_hi.b_lo  (f32 accum, mma.sync bf16)
// grid (NSLOT, 8): blockIdx.y = M-stripe (256 rows, A resident in SMEM),
// blockIdx.x = N slot; CTA walks n-tiles bx, bx+18, ... double-buffered cp.async.
__global__ void __launch_bounds__(256, 1) k_gemm(float* __restrict__ out){
    extern __shared__ char smem[];
    const uint32_t sb = smem_u32(smem);
    const int t = threadIdx.x;
    const int m_base = blockIdx.y * 256;

    // resident A loads (hi & lo)
    {
        const char* gAhi = (const char*)g_Ahi4 + (size_t)m_base*256;
        const char* gAlo = (const char*)g_Alo4 + (size_t)m_base*256;
        #pragma unroll
        for (int i = 0; i < 16; i++){
            int idx = i*256 + t, r = idx >> 4, c = idx & 15;
            cp_async16(sb + OFF_A0 + r*ROWB + c*16, gAhi + (size_t)idx*16);
            cp_async16(sb + OFF_A1 + r*ROWB + c*16, gAlo + (size_t)idx*16);
        }
    }
    // first B tile into buffer 0
    int nt = blockIdx.x;
    {
        const char* gh = (const char*)g_Bhi4 + (size_t)nt*GT_N*256;
        const char* gl = (const char*)g_Blo4 + (size_t)nt*GT_N*256;
        #pragma unroll
        for (int i = 0; i < 4; i++){
            int idx = i*256 + t, r = idx >> 4, c = idx & 15;
            cp_async16(sb + OFF_B + r*ROWB + c*16,        gh + (size_t)idx*16);
            cp_async16(sb + OFF_B + B_SZ + r*ROWB + c*16, gl + (size_t)idx*16);
        }
    }
    CP_COMMIT();
    CP_WAIT(0);
    __syncthreads();

    const int lane = t & 31, wid = t >> 5;
    const int wm = wid >> 1, wn = wid & 1;            // 4 x 2 warps -> 64x32 tiles
    const uint32_t lmo = (uint32_t)((lane & 15)*ROWB + (lane >> 4)*16);
    const uint32_t aW = (uint32_t)(wm*64*ROWB);
    const uint32_t bW = (uint32_t)(wn*32*ROWB);
    const int gID = lane >> 2, tig = lane & 3;

    int cur = 0;
    while (nt < N_NT){
        int nnt = nt + NSLOT;
        if (nnt < N_NT){
            uint32_t dst = sb + OFF_B + (uint32_t)((cur^1)*2*B_SZ);
            const char* gh = (const char*)g_Bhi4 + (size_t)nnt*GT_N*256;
            const char* gl = (const char*)g_Blo4 + (size_t)nnt*GT_N*256;
            #pragma unroll
            for (int i = 0; i < 4; i++){
                int idx = i*256 + t, r = idx >> 4, c = idx & 15;
                cp_async16(dst + r*ROWB + c*16,        gh + (size_t)idx*16);
                cp_async16(dst + B_SZ + r*ROWB + c*16, gl + (size_t)idx*16);
            }
        }
        CP_COMMIT();

        float acc[4][4][4];
        #pragma unroll
        for (int mi = 0; mi < 4; mi++)
            #pragma unroll
            for (int n8 = 0; n8 < 4; n8++)
                #pragma unroll
                for (int q = 0; q < 4; q++) acc[mi][n8][q] = 0.f;

        const uint32_t bb = sb + OFF_B + (uint32_t)(cur*2*B_SZ);

        #define DO_PASS(ABASE, BBASE) do { \
            uint32_t aB = (ABASE) + aW + lmo; \
            uint32_t bB = (BBASE) + bW + lmo; \
            _Pragma("unroll") \
            for (int ks = 0; ks < 8; ks++){ \
                uint32_t ua[4][4], ub[2][4]; \
                _Pragma("unroll") \
                for (int mi = 0; mi < 4; mi++) \
                    ldsm_x4(ua[mi], aB + mi*16*ROWB + ks*32); \
                _Pragma("unroll") \
                for (int nj = 0; nj < 2; nj++) \
                    ldsm_x4(ub[nj], bB + nj*16*ROWB + ks*32); \
                _Pragma("unroll") \
                for (int mi = 0; mi < 4; mi++) \
                    _Pragma("unroll") \
                    for (int n8 = 0; n8 < 4; n8++) \
                        mma16816(acc[mi][n8], ua[mi], \
                                 ub[n8>>1][n8&1], ub[n8>>1][2+(n8&1)]); \
            } } while(0)

        DO_PASS(sb + OFF_A0, bb);            // a_hi . b_hi
        DO_PASS(sb + OFF_A1, bb);            // a_lo . b_hi
        DO_PASS(sb + OFF_A0, bb + B_SZ);     // a_hi . b_lo
        #undef DO_PASS

        // epilogue
        #pragma unroll
        for (int n8 = 0; n8 < 4; n8++){
            int v = nt*GT_N + wn*32 + n8*8 + tig*2;
            if (v < VOC){
                float2 cc = *(const float2*)(g_c + v);
                #pragma unroll
                for (int mi = 0; mi < 4; mi++){
                    int r0 = m_base + wm*64 + mi*16 + gID;
                    float2 d0 = { acc[mi][n8][0] + cc.x, acc[mi][n8][1] + cc.y };
                    float2 d1 = { acc[mi][n8][2] + cc.x, acc[mi][n8][3] + cc.y };
                    *(float2*)(out + (size_t)r0*VOC + v)     = d0;
                    *(float2*)(out + (size_t)(r0+8)*VOC + v) = d1;
                }
            }
        }

        CP_WAIT(0);
        __syncthreads();
        cur ^= 1;
        nt = nnt;
    }
}

// ---------------- launch ----------------
extern "C" void kernel_launch(void* const* d_in, const int* in_sizes, int n_in,
                              void* d_out, int out_size){
    const int*   su    = (const int*)  d_in[0];
    const float* emb   = (const float*)d_in[1];
    const float* convK = (const float*)d_in[2];
    const float* convb = (const float*)d_in[3];
    const float* fc1W  = (const float*)d_in[7];
    const float* fc1b  = (const float*)d_in[8];
    const float* fc2W  = (const float*)d_in[9];
    const float* fc2b  = (const float*)d_in[10];
    float* out = (float*)d_out;

    (void)in_sizes; (void)n_in; (void)out_size;

    cudaFuncSetAttribute(k_gemm, cudaFuncAttributeMaxDynamicSharedMemorySize, SMEM_TOTAL);

    k_eu_partial<<<NPART, 128>>>(su, emb);
    k_eu_final<<<1, 128>>>();
    k_mid<<<SDIM/MPOS, 128>>>(su, emb, convK, convb, fc1W, fc1b);
    k_prepB<<<(NPADV*32 + 255)/256, 256>>>(fc2W);
    k_cvec<<<VOC/8, 256>>>(fc2W, fc2b);
    k_gemm<<<dim3(NSLOT, 8), 256, SMEM_TOTAL>>>(out);
}